// round 1
// baseline (speedup 1.0000x reference)
#include <cuda_runtime.h>

// Problem constants (fixed by dataset: B=16, H=1024, W=2048, G=8, C=19)
#define NB      524288          // number of 8x8 label blocks = 16*128*256
#define NC      19
#define WID     2048
#define HEI     1024
#define GS      8
#define WB      (WID/GS)        // 256 blocks along W
#define HB      (HEI/GS)        // 128 blocks along H
#define NELEM   (NB*NC)         // 9961472 (pred elements)
#define NTHB    (NELEM/4)       // 2490368 float4 threads
#define CTAS_B  (NTHB/256)      // 9728 CTAs (exact)

// Allocation-free scratch (__device__ globals per harness rules)
__device__ unsigned int g_masks[NB + 4];
__device__ double       g_partials[CTAS_B];

// ---------------------------------------------------------------------------
// Kernel 1: per-block 19-bit presence mask from targets.
// One thread per 8x8 block: 16x LDG.128 (int4), 64x (shift|or).
// Consecutive threads -> consecutive 32B chunks along W: coalesced, all bytes used.
// ---------------------------------------------------------------------------
__global__ void __launch_bounds__(256) mask_kernel(const int* __restrict__ tgt)
{
    unsigned int t  = blockIdx.x * 256u + threadIdx.x;
    unsigned int bw = t & (WB - 1);          // 0..255
    unsigned int bh = (t >> 8) & (HB - 1);   // 0..127
    unsigned int b  = t >> 15;               // 0..15

    size_t base = ((size_t)(b * HEI + bh * GS)) * WID + (size_t)bw * GS;
    const int4* p = (const int4*)(tgt + base);   // 16B-aligned: base multiple of 8 ints

    unsigned int m = 0u;
#pragma unroll
    for (int r = 0; r < 8; r++) {
        int4 v0 = p[r * (WID / 4)];
        int4 v1 = p[r * (WID / 4) + 1];
        m |= (1u << v0.x) | (1u << v0.y) | (1u << v0.z) | (1u << v0.w);
        m |= (1u << v1.x) | (1u << v1.y) | (1u << v1.z) | (1u << v1.w);
    }
    g_masks[t] = m;
}

// Numerically stable softplus: max(x,0) + log(1 + exp(-|x|))
__device__ __forceinline__ float softplus_f(float x)
{
    float e = __expf(-fabsf(x));
    return fmaxf(x, 0.0f) + __logf(1.0f + e);
}

// ---------------------------------------------------------------------------
// Kernel 2: loss over flat preds array, one float4 per thread (coalesced).
// loss(x, t) = softplus(x) - t*x  (t = presence bit)
// Deterministic reduction: warp shuffle -> smem -> per-CTA double partial.
// ---------------------------------------------------------------------------
__global__ void __launch_bounds__(256) loss_kernel(const float* __restrict__ preds)
{
    unsigned int j  = blockIdx.x * 256u + threadIdx.x;     // < NTHB
    unsigned int e0 = j * 4u;                              // flat element index
    unsigned int q  = e0 / 19u;                            // block index (magic div)
    unsigned int c0 = e0 - q * 19u;                        // class of first element

    float4 x = ((const float4*)preds)[j];
    unsigned int m0 = g_masks[q];
    unsigned int m1 = g_masks[q + 1];                      // safe: padded array

    float xs0 = x.x, xs1 = x.y, xs2 = x.z, xs3 = x.w;
    float s = 0.0f;
#pragma unroll
    for (int k = 0; k < 4; k++) {
        float xv = (k == 0) ? xs0 : (k == 1) ? xs1 : (k == 2) ? xs2 : xs3;
        unsigned int c  = c0 + (unsigned int)k;
        unsigned int mm = m0;
        if (c >= 19u) { c -= 19u; mm = m1; }
        float sp = softplus_f(xv);
        s += ((mm >> c) & 1u) ? (sp - xv) : sp;
    }

    // warp reduce
#pragma unroll
    for (int o = 16; o > 0; o >>= 1)
        s += __shfl_xor_sync(0xffffffffu, s, o);

    __shared__ float ws[8];
    if ((threadIdx.x & 31u) == 0u) ws[threadIdx.x >> 5] = s;
    __syncthreads();
    if (threadIdx.x < 32u) {
        float v = (threadIdx.x < 8u) ? ws[threadIdx.x] : 0.0f;
#pragma unroll
        for (int o = 4; o > 0; o >>= 1)
            v += __shfl_xor_sync(0xffffffffu, v, o);
        if (threadIdx.x == 0u)
            g_partials[blockIdx.x] = (double)v;
    }
}

// ---------------------------------------------------------------------------
// Kernel 3: deterministic final reduction of per-CTA partials -> mean -> d_out
// ---------------------------------------------------------------------------
__global__ void __launch_bounds__(256) final_kernel(float* __restrict__ out)
{
    double s = 0.0;
    for (unsigned int i = threadIdx.x; i < (unsigned int)CTAS_B; i += 256u)
        s += g_partials[i];

    __shared__ double sh[256];
    sh[threadIdx.x] = s;
    __syncthreads();
#pragma unroll
    for (int o = 128; o > 0; o >>= 1) {
        if (threadIdx.x < (unsigned int)o) sh[threadIdx.x] += sh[threadIdx.x + o];
        __syncthreads();
    }
    if (threadIdx.x == 0)
        out[0] = (float)(sh[0] / ((double)NB * (double)NC));
}

// ---------------------------------------------------------------------------
extern "C" void kernel_launch(void* const* d_in, const int* in_sizes, int n_in,
                              void* d_out, int out_size)
{
    const float* preds = (const float*)d_in[0];
    const int*   tgt   = (const int*)d_in[1];
    // d_in[2] = grid_size (always 8 for this problem's shapes)

    mask_kernel<<<NB / 256, 256>>>(tgt);
    loss_kernel<<<CTAS_B, 256>>>(preds);
    final_kernel<<<1, 256>>>((float*)d_out);
}